// round 5
// baseline (speedup 1.0000x reference)
#include <cuda_runtime.h>
#include <cuda_bf16.h>
#include <math.h>
#include <stdint.h>

#define NB 4
#define NS 4000
#define NDIN 1024
#define NDA 512
#define NL 8921
#define SPAD 4096   // padded S
#define LPAD 8960   // padded L (70 * 128)
#define KCH 64      // bf16 K elements per pipeline chunk
#define STG 65536   // bytes per stage: 4 x 16KB buffers (Ahi,Alo,Bhi,Blo)
#define NSTAGE 3

// ---------------------------------------------------------------------------
// Scratch (device globals: zero-initialized at module load; padded regions are
// never written so they stay zero -> no bounds checks in GEMM operand loads).
// ---------------------------------------------------------------------------
__device__ float g_z[(size_t)NB * NS * NDA];
__device__ __nv_bfloat16 g_xhi[(size_t)NB * NS * NDIN];    // x hi  [b*s][din]
__device__ __nv_bfloat16 g_xlo[(size_t)NB * NS * NDIN];
__device__ __nv_bfloat16 g_Whi[(size_t)NDA * NDIN];        // W hi  [a][din]
__device__ __nv_bfloat16 g_Wlo[(size_t)NDA * NDIN];
__device__ __nv_bfloat16 g_zhi[(size_t)NB * SPAD * NDA];   // z hi  [b][s][a]
__device__ __nv_bfloat16 g_zlo[(size_t)NB * SPAD * NDA];
__device__ __nv_bfloat16 g_zThi[(size_t)NB * NDA * SPAD];  // z^T hi [b][a][s]
__device__ __nv_bfloat16 g_zTlo[(size_t)NB * NDA * SPAD];
__device__ __nv_bfloat16 g_Uhi[(size_t)LPAD * NDA];
__device__ __nv_bfloat16 g_Ulo[(size_t)LPAD * NDA];
__device__ __nv_bfloat16 g_ahi[(size_t)NB * LPAD * SPAD];  // alpha hi (padded)
__device__ __nv_bfloat16 g_alo[(size_t)NB * LPAD * SPAD];
__device__ float g_m[(size_t)NB * NL * NDA];

// ---------------------------------------------------------------------------
// Helpers
// ---------------------------------------------------------------------------
__device__ __forceinline__ uint32_t smem_u32(const void* p) {
    uint32_t a;
    asm("{ .reg .u64 t; cvta.to.shared.u64 t, %1; cvt.u32.u64 %0, t; }"
        : "=r"(a) : "l"(p));
    return a;
}
__device__ __forceinline__ void cpa16(uint32_t dst, const void* src) {
    asm volatile("cp.async.cg.shared.global [%0], [%1], 16;"
                 :: "r"(dst), "l"(src) : "memory");
}
#define CP_COMMIT() asm volatile("cp.async.commit_group;" ::: "memory")
#define CP_WAIT(n)  asm volatile("cp.async.wait_group %0;" :: "n"(n) : "memory")

__device__ __forceinline__ void ldsm4(uint32_t& r0, uint32_t& r1,
                                      uint32_t& r2, uint32_t& r3, uint32_t addr) {
    asm volatile("ldmatrix.sync.aligned.m8n8.x4.shared.b16 {%0,%1,%2,%3}, [%4];"
                 : "=r"(r0), "=r"(r1), "=r"(r2), "=r"(r3) : "r"(addr));
}
__device__ __forceinline__ void mma16816(float* d, const uint32_t* a, const uint32_t* b) {
    asm volatile(
        "mma.sync.aligned.m16n8k16.row.col.f32.bf16.bf16.f32 "
        "{%0,%1,%2,%3}, {%4,%5,%6,%7}, {%8,%9}, {%0,%1,%2,%3};"
        : "+f"(d[0]), "+f"(d[1]), "+f"(d[2]), "+f"(d[3])
        : "r"(a[0]), "r"(a[1]), "r"(a[2]), "r"(a[3]), "r"(b[0]), "r"(b[1]));
}

__device__ __forceinline__ void split_bf16(float v, __nv_bfloat16& hi, __nv_bfloat16& lo) {
    hi = __float2bfloat16(v);
    lo = __float2bfloat16(v - __bfloat162float(hi));
}
__device__ __forceinline__ uint32_t pack2(__nv_bfloat16 a, __nv_bfloat16 b) {
    return (uint32_t)__bfloat16_as_ushort(a) | ((uint32_t)__bfloat16_as_ushort(b) << 16);
}

// Swizzled offset inside a 128-row x 64-col bf16 buffer (128B rows, 8 x 16B
// groups, group ^= row&7 -> ldmatrix phases and cp.async writes conflict-free).
__device__ __forceinline__ uint32_t swoff(int row, int c16) {
    return (uint32_t)(row * 128 + ((c16 ^ (row & 7)) * 16));
}

// ---------------------------------------------------------------------------
// bf16x3 tensor-core GEMM via mma.sync:
//   D[M,N] = sum_k (Ahi+Alo)[m,k]*(Bhi+Blo)[n,k]   (Alo*Blo dropped)
// CTA tile 128x128, 8 warps (2x4), warp tile 64x32, K-chunk 64,
// 3-stage cp.async pipeline, one __syncthreads per chunk.
// Warp-groups process the 4 kk sub-steps in rotated order so the two warps
// sharing an SMSP anti-align their LDSM and MMA phases.
// Optional epilogue: tanh(acc + bias[n]).
// ---------------------------------------------------------------------------
template <bool TANH>
__global__ __launch_bounds__(256, 1)
void gemm_mma(const __nv_bfloat16* __restrict__ Ahi, const __nv_bfloat16* __restrict__ Alo,
              const __nv_bfloat16* __restrict__ Bhi, const __nv_bfloat16* __restrict__ Blo,
              float* __restrict__ C, const float* __restrict__ bias,
              int nk, int Mvalid, int Nvalid, int ldA, int ldB, int ldC,
              long long sA, long long sB, long long sC)
{
    extern __shared__ char smem[];
    const uint32_t sb = smem_u32(smem);

    const int t = threadIdx.x, w = t >> 5, lane = t & 31;
    const int m0 = blockIdx.y * 128, n0 = blockIdx.x * 128, b = blockIdx.z;
    const int wm = (w >> 2) * 64, wn = (w & 3) * 32;
    const int rot = (w >> 2) << 1;   // warps 0-3: kk order 0123; warps 4-7: 2301

    const __nv_bfloat16* Ah = Ahi + b * sA + (long long)m0 * ldA;
    const __nv_bfloat16* Al = Alo + b * sA + (long long)m0 * ldA;
    const __nv_bfloat16* Bh = Bhi + b * sB + (long long)n0 * ldB;
    const __nv_bfloat16* Bl = Blo + b * sB + (long long)n0 * ldB;
    float* Cb = C + b * sC;

    float acc[4][4][4];
#pragma unroll
    for (int i = 0; i < 4; i++)
#pragma unroll
        for (int j = 0; j < 4; j++)
#pragma unroll
            for (int q = 0; q < 4; q++) acc[i][j][q] = 0.f;

    // stage layout: +0 Ahi, +16K Alo, +32K Bhi, +48K Blo  (each 128x64 bf16)
    auto load_stage = [&](int c, int s) {
        const uint32_t st = sb + s * STG;
        const int kb = c * KCH;
#pragma unroll
        for (int j = 0; j < 4; j++) {
            const int cid = t + 256 * j;                 // 0..1023
            const int row = cid >> 3, c16 = cid & 7;
            const uint32_t sw = swoff(row, c16);
            const long long ga = (long long)row * ldA + kb + c16 * 8;
            const long long gb = (long long)row * ldB + kb + c16 * 8;
            cpa16(st + sw,             Ah + ga);
            cpa16(st + 16384 + sw,     Al + ga);
            cpa16(st + 32768 + sw,     Bh + gb);
            cpa16(st + 49152 + sw,     Bl + gb);
        }
    };

    load_stage(0, 0); CP_COMMIT();
    load_stage(1, 1); CP_COMMIT();

    for (int c = 0; c < nk; c++) {
        const int s = c % NSTAGE;
        if (c == nk - 1) { CP_WAIT(0); } else { CP_WAIT(1); }
        __syncthreads();           // stage s published; stage (c+2)%3 free
        if (c + 2 < nk) { load_stage(c + 2, (c + 2) % NSTAGE); CP_COMMIT(); }

        const uint32_t stAh = sb + s * STG;
        const uint32_t stAl = stAh + 16384;
        const uint32_t stBh = stAh + 32768;
        const uint32_t stBl = stAh + 49152;

        const int rA = lane & 15, chA = lane >> 4;
        const int r8 = ((lane >> 4) << 3) + (lane & 7);
        const int chB = (lane >> 3) & 1;

#pragma unroll
        for (int kki = 0; kki < 4; kki++) {
            const int kk = (kki + rot) & 3;

            // B hi fragments first (smallest dependency set for first MMAs)
            uint32_t bh[4][2];
#pragma unroll
            for (int nh = 0; nh < 2; nh++) {
                const uint32_t off = swoff(wn + nh * 16 + r8, kk * 2 + chB);
                uint32_t r0, r1, r2, r3;
                ldsm4(r0, r1, r2, r3, stBh + off);
                bh[nh * 2][0] = r0; bh[nh * 2][1] = r1;
                bh[nh * 2 + 1][0] = r2; bh[nh * 2 + 1][1] = r3;
            }
            // A hi fragments
            uint32_t ah[4][4];
#pragma unroll
            for (int mt = 0; mt < 4; mt++) {
                const uint32_t off = swoff(wm + mt * 16 + rA, kk * 2 + chA);
                ldsm4(ah[mt][0], ah[mt][1], ah[mt][2], ah[mt][3], stAh + off);
            }
            // hi x hi
#pragma unroll
            for (int mt = 0; mt < 4; mt++)
#pragma unroll
                for (int nt = 0; nt < 4; nt++)
                    mma16816(acc[mt][nt], ah[mt], bh[nt]);

            // A lo fragments, then lo x hi
            uint32_t al[4][4];
#pragma unroll
            for (int mt = 0; mt < 4; mt++) {
                const uint32_t off = swoff(wm + mt * 16 + rA, kk * 2 + chA);
                ldsm4(al[mt][0], al[mt][1], al[mt][2], al[mt][3], stAl + off);
            }
#pragma unroll
            for (int mt = 0; mt < 4; mt++)
#pragma unroll
                for (int nt = 0; nt < 4; nt++)
                    mma16816(acc[mt][nt], al[mt], bh[nt]);

            // B lo fragments, then hi x lo
            uint32_t bl[4][2];
#pragma unroll
            for (int nh = 0; nh < 2; nh++) {
                const uint32_t off = swoff(wn + nh * 16 + r8, kk * 2 + chB);
                uint32_t r0, r1, r2, r3;
                ldsm4(r0, r1, r2, r3, stBl + off);
                bl[nh * 2][0] = r0; bl[nh * 2][1] = r1;
                bl[nh * 2 + 1][0] = r2; bl[nh * 2 + 1][1] = r3;
            }
#pragma unroll
            for (int mt = 0; mt < 4; mt++)
#pragma unroll
                for (int nt = 0; nt < 4; nt++)
                    mma16816(acc[mt][nt], ah[mt], bl[nt]);
        }
    }

    // Epilogue
#pragma unroll
    for (int mt = 0; mt < 4; mt++) {
        const int r0g = m0 + wm + mt * 16 + (lane >> 2);
        const int r1g = r0g + 8;
#pragma unroll
        for (int nt = 0; nt < 4; nt++) {
            const int cg = n0 + wn + nt * 8 + (lane & 3) * 2;
            if (cg < Nvalid) {
                float2 v0 = make_float2(acc[mt][nt][0], acc[mt][nt][1]);
                float2 v1 = make_float2(acc[mt][nt][2], acc[mt][nt][3]);
                if (TANH) {
                    const float b0v = bias[cg], b1v = bias[cg + 1];
                    v0.x = tanhf(v0.x + b0v); v0.y = tanhf(v0.y + b1v);
                    v1.x = tanhf(v1.x + b0v); v1.y = tanhf(v1.y + b1v);
                }
                if (r0g < Mvalid) *(float2*)(Cb + (long long)r0g * ldC + cg) = v0;
                if (r1g < Mvalid) *(float2*)(Cb + (long long)r1g * ldC + cg) = v1;
            }
        }
    }
}

// ---------------------------------------------------------------------------
// fp32 -> bf16 hi/lo flat splitters
// ---------------------------------------------------------------------------
__global__ __launch_bounds__(256)
void split_flat(const float* __restrict__ src, __nv_bfloat16* __restrict__ dhi,
                __nv_bfloat16* __restrict__ dlo, long long n)
{
    const long long i = ((long long)blockIdx.x * 256 + threadIdx.x) * 4;
    if (i >= n) return;
    float4 v = *(const float4*)(src + i);
    __nv_bfloat16 h[4], l[4];
    split_bf16(v.x, h[0], l[0]); split_bf16(v.y, h[1], l[1]);
    split_bf16(v.z, h[2], l[2]); split_bf16(v.w, h[3], l[3]);
    uint2 ph, pl;
    ph.x = pack2(h[0], h[1]); ph.y = pack2(h[2], h[3]);
    pl.x = pack2(l[0], l[1]); pl.y = pack2(l[2], l[3]);
    *(uint2*)(dhi + i) = ph;
    *(uint2*)(dlo + i) = pl;
}

// ---------------------------------------------------------------------------
// z fp32 -> bf16 hi/lo (padded row-major) + transposed hi/lo
// ---------------------------------------------------------------------------
__global__ __launch_bounds__(256)
void zconv(const float* __restrict__ z)
{
    __shared__ __nv_bfloat16 shi[32][33];
    __shared__ __nv_bfloat16 slo[32][33];
    const int b = blockIdx.z;
    const int s0 = blockIdx.x * 32, a0 = blockIdx.y * 32;
    const int t = threadIdx.x;
    const int r = t >> 3, c = (t & 7) * 4;

    float4 v = *(const float4*)(z + ((long long)b * NS + s0 + r) * NDA + a0 + c);
    __nv_bfloat16 h[4], l[4];
    split_bf16(v.x, h[0], l[0]); split_bf16(v.y, h[1], l[1]);
    split_bf16(v.z, h[2], l[2]); split_bf16(v.w, h[3], l[3]);

    uint2 ph, pl;
    ph.x = pack2(h[0], h[1]); ph.y = pack2(h[2], h[3]);
    pl.x = pack2(l[0], l[1]); pl.y = pack2(l[2], l[3]);
    const long long ro = ((long long)b * SPAD + s0 + r) * NDA + a0 + c;
    *(uint2*)(g_zhi + ro) = ph;
    *(uint2*)(g_zlo + ro) = pl;

#pragma unroll
    for (int i = 0; i < 4; i++) { shi[r][c + i] = h[i]; slo[r][c + i] = l[i]; }
    __syncthreads();

    __nv_bfloat16 th[4], tl[4];
#pragma unroll
    for (int i = 0; i < 4; i++) { th[i] = shi[c + i][r]; tl[i] = slo[c + i][r]; }
    uint2 qh, ql;
    qh.x = pack2(th[0], th[1]); qh.y = pack2(th[2], th[3]);
    ql.x = pack2(tl[0], tl[1]); ql.y = pack2(tl[2], tl[3]);
    const long long to = ((long long)b * NDA + a0 + r) * SPAD + s0 + c;
    *(uint2*)(g_zThi + to) = qh;
    *(uint2*)(g_zTlo + to) = ql;
}

// ---------------------------------------------------------------------------
// Softmax over S per (b,l) row; writes fp32 alpha + bf16 hi/lo copies
// ---------------------------------------------------------------------------
__global__ __launch_bounds__(256)
void softmax_kernel(float* __restrict__ alpha)
{
    __shared__ float buf[NS];
    __shared__ float red[8];
    const int bl = blockIdx.x;
    const int b = bl / NL, l = bl % NL;
    float* p = alpha + (long long)bl * NS;
    __nv_bfloat16* ah = g_ahi + ((long long)b * LPAD + l) * SPAD;
    __nv_bfloat16* al = g_alo + ((long long)b * LPAD + l) * SPAD;
    const int t = threadIdx.x;
    const int lane = t & 31, wid = t >> 5;

    float mx = -3.4e38f;
    for (int i = t * 4; i < NS; i += 1024) {
        float4 v = *(const float4*)(p + i);
        *(float4*)(buf + i) = v;
        mx = fmaxf(fmaxf(mx, v.x), fmaxf(fmaxf(v.y, v.z), v.w));
    }
#pragma unroll
    for (int o = 16; o; o >>= 1) mx = fmaxf(mx, __shfl_xor_sync(0xffffffffu, mx, o));
    if (lane == 0) red[wid] = mx;
    __syncthreads();
    if (wid == 0) {
        float m2 = (lane < 8) ? red[lane] : -3.4e38f;
#pragma unroll
        for (int o = 4; o; o >>= 1) m2 = fmaxf(m2, __shfl_xor_sync(0xffffffffu, m2, o));
        if (lane == 0) red[0] = m2;
    }
    __syncthreads();
    mx = red[0];
    __syncthreads();

    float s = 0.f;
    for (int i = t * 4; i < NS; i += 1024) {
        float4 v = *(const float4*)(buf + i);
        v.x = __expf(v.x - mx); v.y = __expf(v.y - mx);
        v.z = __expf(v.z - mx); v.w = __expf(v.w - mx);
        *(float4*)(buf + i) = v;
        s += (v.x + v.y) + (v.z + v.w);
    }
#pragma unroll
    for (int o = 16; o; o >>= 1) s += __shfl_xor_sync(0xffffffffu, s, o);
    if (lane == 0) red[wid] = s;
    __syncthreads();
    if (wid == 0) {
        float s2 = (lane < 8) ? red[lane] : 0.f;
#pragma unroll
        for (int o = 4; o; o >>= 1) s2 += __shfl_xor_sync(0xffffffffu, s2, o);
        if (lane == 0) red[0] = s2;
    }
    __syncthreads();
    const float inv = 1.f / red[0];

    for (int i = t * 4; i < NS; i += 1024) {
        float4 v = *(const float4*)(buf + i);
        v.x *= inv; v.y *= inv; v.z *= inv; v.w *= inv;
        *(float4*)(p + i) = v;
        __nv_bfloat16 h[4], lo[4];
        split_bf16(v.x, h[0], lo[0]); split_bf16(v.y, h[1], lo[1]);
        split_bf16(v.z, h[2], lo[2]); split_bf16(v.w, h[3], lo[3]);
        uint2 ph, pl;
        ph.x = pack2(h[0], h[1]); ph.y = pack2(h[2], h[3]);
        pl.x = pack2(lo[0], lo[1]); pl.y = pack2(lo[2], lo[3]);
        *(uint2*)(ah + i) = ph;
        *(uint2*)(al + i) = pl;
    }
}

// ---------------------------------------------------------------------------
// y[b,l] = dot(V[l], m[b,l]) + V_b[l]
// ---------------------------------------------------------------------------
__global__ __launch_bounds__(128)
void y_kernel(const float* __restrict__ Vw, const float* __restrict__ Vb,
              const float* __restrict__ mbuf, float* __restrict__ y)
{
    __shared__ float red[4];
    const int row = blockIdx.x;
    const int l = row % NL;
    const float* mr = mbuf + (long long)row * NDA;
    const float* vr = Vw + (long long)l * NDA;
    const int t = threadIdx.x;

    float s = 0.f;
    for (int i = t; i < NDA; i += 128) s = fmaf(vr[i], mr[i], s);
#pragma unroll
    for (int o = 16; o; o >>= 1) s += __shfl_xor_sync(0xffffffffu, s, o);
    const int lane = t & 31, wid = t >> 5;
    if (lane == 0) red[wid] = s;
    __syncthreads();
    if (t == 0) y[row] = ((red[0] + red[1]) + (red[2] + red[3])) + Vb[l];
}

// ---------------------------------------------------------------------------
extern "C" void kernel_launch(void* const* d_in, const int* in_sizes, int n_in,
                              void* d_out, int out_size)
{
    const float* x  = (const float*)d_in[0];
    const float* Ww = (const float*)d_in[1];
    const float* Wb = (const float*)d_in[2];
    const float* Uw = (const float*)d_in[3];
    const float* Vw = (const float*)d_in[4];
    const float* Vb = (const float*)d_in[5];

    float* y     = (float*)d_out;
    float* alpha = (float*)d_out + (size_t)NB * NL;

    float *zbuf, *mbuf;
    __nv_bfloat16 *xhi, *xlo, *whi, *wlo, *zhi, *zlo, *zThi, *zTlo, *uhi, *ulo, *ahi, *alo;
    cudaGetSymbolAddress((void**)&zbuf, g_z);
    cudaGetSymbolAddress((void**)&mbuf, g_m);
    cudaGetSymbolAddress((void**)&xhi, g_xhi);
    cudaGetSymbolAddress((void**)&xlo, g_xlo);
    cudaGetSymbolAddress((void**)&whi, g_Whi);
    cudaGetSymbolAddress((void**)&wlo, g_Wlo);
    cudaGetSymbolAddress((void**)&zhi, g_zhi);
    cudaGetSymbolAddress((void**)&zlo, g_zlo);
    cudaGetSymbolAddress((void**)&zThi, g_zThi);
    cudaGetSymbolAddress((void**)&zTlo, g_zTlo);
    cudaGetSymbolAddress((void**)&uhi, g_Uhi);
    cudaGetSymbolAddress((void**)&ulo, g_Ulo);
    cudaGetSymbolAddress((void**)&ahi, g_ahi);
    cudaGetSymbolAddress((void**)&alo, g_alo);

    cudaFuncSetAttribute(gemm_mma<false>, cudaFuncAttributeMaxDynamicSharedMemorySize,
                         NSTAGE * STG);
    cudaFuncSetAttribute(gemm_mma<true>, cudaFuncAttributeMaxDynamicSharedMemorySize,
                         NSTAGE * STG);

    // 1) split x and W into bf16 hi/lo
    {
        long long nx = (long long)NB * NS * NDIN;
        split_flat<<<(unsigned)((nx / 4 + 255) / 256), 256>>>(x, xhi, xlo, nx);
        long long nw = (long long)NDA * NDIN;
        split_flat<<<(unsigned)((nw / 4 + 255) / 256), 256>>>(Ww, whi, wlo, nw);
    }
    // 2) split U into bf16 hi/lo
    {
        long long nu = (long long)NL * NDA;
        split_flat<<<(unsigned)((nu / 4 + 255) / 256), 256>>>(Uw, uhi, ulo, nu);
    }
    // 3) z = tanh(x @ W^T + b)  via bf16x3 MMA  [16000, 512]
    {
        dim3 g(NDA / 128, (NB * NS) / 128, 1);
        gemm_mma<true><<<g, 256, NSTAGE * STG>>>(
            xhi, xlo, whi, wlo, zbuf, Wb,
            NDIN / KCH, NB * NS, NDA, NDIN, NDIN, NDA, 0LL, 0LL, 0LL);
    }
    // 4) z -> bf16 hi/lo + transposed hi/lo
    {
        dim3 g(NS / 32, NDA / 32, NB);
        zconv<<<g, 256>>>(zbuf);
    }
    // 5) scores = U @ z^T (bf16x3) -> alpha region of d_out
    {
        dim3 g(SPAD / 128, LPAD / 128, NB);
        gemm_mma<false><<<g, 256, NSTAGE * STG>>>(
            uhi, ulo, zhi, zlo, alpha, nullptr,
            NDA / KCH, NL, NS, NDA, NDA, NS,
            0LL, (long long)SPAD * NDA, (long long)NL * NS);
    }
    // 6) softmax (writes fp32 alpha + bf16 hi/lo copies)
    softmax_kernel<<<NB * NL, 256>>>(alpha);

    // 7) m = alpha @ z (bf16x3). K runs to 4032 (ceil(4000/64)); alpha pad
    //    cols 4000..4031 are zero, cols 4032..4095 skipped entirely.
    {
        dim3 g(NDA / 128, LPAD / 128, NB);
        gemm_mma<false><<<g, 256, NSTAGE * STG>>>(
            ahi, alo, zThi, zTlo, mbuf, nullptr,
            63, NL, NDA, SPAD, SPAD, NDA,
            (long long)LPAD * SPAD, (long long)NDA * SPAD, (long long)NL * NDA);
    }
    // 8) y
    y_kernel<<<NB * NL, 128>>>(Vw, Vb, mbuf, y);
}